// round 12
// baseline (speedup 1.0000x reference)
#include <cuda_runtime.h>
#include <cuda_bf16.h>

// out[n, j] = x[n, j] + (1/512) * sum_{k=512..1023} x[n, k]
// x: [131072, 1024] f32, out: [131072, 512] f32
//
// Persistent grid-stride variant of the converged R11 config:
//   - 1184 CTAs (8/SM x 148), each loops over 2-row work items.
//     Eliminates wave-transition + CTA-launch overhead of the 65536-block
//     grid (the only remaining cost: steady-state DRAM is saturated ~88%).
//   - Loop body identical to best-measured: 2 rows x 128 threads, __ldcg
//     loads (L1 bypass, zero-reuse data), one __syncthreads, plain store.
//   - smem partials double-buffered by iteration parity -> no 2nd barrier,
//     no WAR hazard across iterations.
//   - NO software pipelining (R4 showed it costs registers for nothing:
//     occupancy already covers the per-iteration tail).

static constexpr int ROW_IN  = 1024;
static constexpr int ROW_OUT = 512;
static constexpr int THREADS = 256;        // 2 rows x 128 threads
static constexpr int GRID    = 148 * 8;    // 1184 CTAs, ~8/SM

__global__ __launch_bounds__(THREADS)
void projection_kernel(const float* __restrict__ x,
                       float* __restrict__ out,
                       int n_pairs)
{
    int sub  = threadIdx.x >> 7;           // row group 0/1
    int tid  = threadIdx.x & 127;          // 0..127 within group
    int lane = threadIdx.x & 31;
    int warp = (threadIdx.x >> 5) & 3;     // warp within group

    __shared__ float partial[2][2][4];     // [parity][sub][warp]

    int buf = 0;
    for (int pair = blockIdx.x; pair < n_pairs; pair += GRID, buf ^= 1) {
        size_t row = (size_t)pair * 2 + sub;

        const float4* xrow = reinterpret_cast<const float4*>(x + row * ROW_IN);
        float4*       orow = reinterpret_cast<float4*>(out + row * ROW_OUT);

        // front-batch both loads, L1-bypass (L2-only) policy
        float4 t = __ldcg(&xrow[128 + tid]);   // tail, feeds reduction
        float4 h = __ldcg(&xrow[tid]);         // head, held for the add

        float s = (t.x + t.y) + (t.z + t.w);

        #pragma unroll
        for (int off = 16; off > 0; off >>= 1)
            s += __shfl_xor_sync(0xFFFFFFFFu, s, off);

        if (lane == 0) partial[buf][sub][warp] = s;
        __syncthreads();

        float total = (partial[buf][sub][0] + partial[buf][sub][1])
                    + (partial[buf][sub][2] + partial[buf][sub][3]);
        float mean = total * (1.0f / 512.0f);

        h.x += mean; h.y += mean; h.z += mean; h.w += mean;

        orow[tid] = h;
    }
}

extern "C" void kernel_launch(void* const* d_in, const int* in_sizes, int n_in,
                              void* d_out, int out_size)
{
    const float* x = (const float*)d_in[0];
    float* out = (float*)d_out;

    int n_rows  = in_sizes[0] / ROW_IN;   // 131072, even
    int n_pairs = n_rows / 2;             // 65536

    projection_kernel<<<GRID, THREADS>>>(x, out, n_pairs);
}

// round 13
// speedup vs baseline: 1.0759x; 1.0759x over previous
#include <cuda_runtime.h>
#include <cuda_bf16.h>

// out[n, j] = x[n, j] + (1/512) * sum_{k=512..1023} x[n, k]
// x: [131072, 1024] f32, out: [131072, 512] f32
//
// FINAL kernel (best wall time measured over 12 rounds: 114.8us).
// 256-thread block = 2 rows x 128 threads, one __syncthreads.
// Per thread: 1 tail float4 + 1 head float4 front-batched (MLP_p1=2, below
// the cross-CTA L1tex contention knee). Streaming cache hints (.cs).
//
// The kernel operates at the HBM read/write-turnaround ceiling: 85-88% of
// 8TB/s spec across every measured configuration; the 768 MiB of traffic is
// irreducible (every byte touched exactly once). Ruled out by measurement:
// persistent grids (+9us wall), named barriers (occupancy collapse),
// deeper MLP (L1tex queue contention), 4-row barrier coupling, software
// pipelining (register pressure for nothing).

static constexpr int ROW_IN  = 1024;
static constexpr int ROW_OUT = 512;
static constexpr int THREADS = 256;              // 2 rows x 128 threads

__global__ __launch_bounds__(THREADS)
void projection_kernel(const float* __restrict__ x,
                       float* __restrict__ out)
{
    // sub-block: which of the 2 rows this thread works on
    int sub  = threadIdx.x >> 7;                  // 0 or 1
    int tid  = threadIdx.x & 127;                 // 0..127 within row
    int lane = threadIdx.x & 31;
    int warp = (threadIdx.x >> 5) & 3;            // warp within sub-block

    size_t row = (size_t)blockIdx.x * 2 + sub;

    const float4* xrow = reinterpret_cast<const float4*>(x + row * ROW_IN);
    float4*       orow = reinterpret_cast<float4*>(out + row * ROW_OUT);

    // ---- front-batch both loads (MLP_p1 = 2) ----
    float4 t = __ldcs(&xrow[128 + tid]);   // tail: feeds reduction
    float4 h = __ldcs(&xrow[tid]);         // head: held for the add

    float s = (t.x + t.y) + (t.z + t.w);

    #pragma unroll
    for (int off = 16; off > 0; off >>= 1)
        s += __shfl_xor_sync(0xFFFFFFFFu, s, off);

    __shared__ float partial[8];           // 4 warps x 2 rows
    if (lane == 0) partial[sub * 4 + warp] = s;
    __syncthreads();

    float total = (partial[sub * 4 + 0] + partial[sub * 4 + 1])
                + (partial[sub * 4 + 2] + partial[sub * 4 + 3]);
    float mean = total * (1.0f / 512.0f);

    h.x += mean; h.y += mean; h.z += mean; h.w += mean;

    __stcs(&orow[tid], h);
}

extern "C" void kernel_launch(void* const* d_in, const int* in_sizes, int n_in,
                              void* d_out, int out_size)
{
    const float* x = (const float*)d_in[0];
    float* out = (float*)d_out;

    int n_rows = in_sizes[0] / ROW_IN;     // 131072, even
    int blocks = n_rows / 2;               // 65536

    projection_kernel<<<blocks, THREADS>>>(x, out);
}